// round 15
// baseline (speedup 1.0000x reference)
#include <cuda_runtime.h>

#define NB 512
#define TT 1024
#define CC 64

typedef unsigned int u32;
typedef unsigned short u16;

__device__ int d_perm[NB];   // batch indices sorted by length (descending)

__device__ __forceinline__ u32 pkbf2(float lo, float hi) {
    u32 r; asm("cvt.rn.bf16x2.f32 %0, %1, %2;" : "=r"(r) : "f"(hi), "f"(lo)); return r;
}
__device__ __forceinline__ u16 f2bf(float x) {
    u16 r; asm("cvt.rn.bf16.f32 %0, %1;" : "=h"(r) : "f"(x)); return r;
}
__device__ __forceinline__ float frcp(float x) {
    float r; asm("rcp.approx.f32 %0, %1;" : "=f"(r) : "f"(x)); return r;
}
__device__ __forceinline__ void mma16816(float& c0, float& c1, float& c2, float& c3,
                                         u32 a0, u32 a1, u32 a2, u32 a3,
                                         u32 b0, u32 b1) {
    asm("mma.sync.aligned.m16n8k16.row.col.f32.bf16.bf16.f32 "
        "{%0,%1,%2,%3}, {%4,%5,%6,%7}, {%8,%9}, {%0,%1,%2,%3};"
        : "+f"(c0), "+f"(c1), "+f"(c2), "+f"(c3)
        : "r"(a0), "r"(a1), "r"(a2), "r"(a3), "r"(b0), "r"(b1));
}

// rank sequences by length (descending, index tie-break); perm[rank] = batch
__global__ void rank_kernel(const int* __restrict__ lengths) {
    __shared__ int L[NB];
    const int tid = threadIdx.x;
    L[tid] = lengths[tid];
    __syncthreads();
    const int mylen = L[tid];
    int rank = 0;
    for (int j = 0; j < NB; ++j) {
        const int lj = L[j];
        rank += (lj > mylen) || (lj == mylen && j < tid);
    }
    d_perm[rank] = tid;
}

__global__ void __launch_bounds__(128, 1) crf_fwd_kernel(
    const float* __restrict__ logits,   // [NB, TT, CC]
    const float* __restrict__ trans,    // [CC, CC]
    const float* __restrict__ init,     // [CC]
    const int*   __restrict__ lengths,  // [NB]
    const int*   __restrict__ tags,     // [NB, TT]
    float*       __restrict__ out)      // [NB]
{
    // per-warp, per-seq bf16 w vectors, double-buffered
    __shared__ __align__(16) u16 wsh[4][2][2][CC];  // [warp][seq][buf][state]

    const int wid  = threadIdx.x >> 5;
    const int lane = threadIdx.x & 31;
    const int w    = blockIdx.x * 4 + wid;          // warp id in [0,256)

    const int gA = d_perm[2 * w];                   // longer sequence
    const int gB = d_perm[2 * w + 1];               // its neighbor in sorted order
    const float* lgA = logits + (size_t)gA * TT * CC;
    const float* lgB = logits + (size_t)gB * TT * CC;
    const int lenA = lengths[gA];
    const int lenB = lengths[gB];                   // lenA >= lenB

    const int gid = lane >> 2;                      // 0..7
    const int tig = lane & 3;                       // 0..3
    const int r1  = gid + 16 * tig;                 // owned states (lane0 -> 0, 8)
    const int r2  = r1 + 8;

    // ---- E = exp(trans) as bf16 A-fragments (shared by both sequences)
    u32 EA[4][4][4];
    #pragma unroll
    for (int mt = 0; mt < 4; ++mt) {
        const int row = 16 * mt + gid;
        #pragma unroll
        for (int kt = 0; kt < 4; ++kt) {
            const int col = 16 * kt + 2 * tig;
            const float e00 = __expf(__ldg(trans + row * CC + col));
            const float e01 = __expf(__ldg(trans + row * CC + col + 1));
            const float e10 = __expf(__ldg(trans + (row + 8) * CC + col));
            const float e11 = __expf(__ldg(trans + (row + 8) * CC + col + 1));
            const float e08 = __expf(__ldg(trans + row * CC + col + 8));
            const float e09 = __expf(__ldg(trans + row * CC + col + 9));
            const float e18 = __expf(__ldg(trans + (row + 8) * CC + col + 8));
            const float e19 = __expf(__ldg(trans + (row + 8) * CC + col + 9));
            EA[mt][kt][0] = pkbf2(e00, e01);
            EA[mt][kt][1] = pkbf2(e10, e11);
            EA[mt][kt][2] = pkbf2(e08, e09);
            EA[mt][kt][3] = pkbf2(e18, e19);
        }
    }

    // ---- w_0 for both sequences
    const float i1 = __ldg(init + r1), i2 = __ldg(init + r2);
    float w1A = __expf(i1 + __ldg(lgA + r1));
    float w2A = __expf(i2 + __ldg(lgA + r2));
    float w1B = __expf(i1 + __ldg(lgB + r1));
    float w2B = __expf(i2 + __ldg(lgB + r2));
    wsh[wid][0][0][r1] = f2bf(w1A); wsh[wid][0][0][r2] = f2bf(w2A);
    wsh[wid][1][0][r1] = f2bf(w1B); wsh[wid][1][0][r2] = f2bf(w2B);
    __syncwarp();

    // ---- logit pipelines (distance-3)
    float F1A = __expf(__ldg(lgA + CC + r1)), F2A = __expf(__ldg(lgA + CC + r2));
    float F1B = __expf(__ldg(lgB + CC + r1)), F2B = __expf(__ldg(lgB + CC + r2));
    const int a2i = (2 < lenA) ? 2 : (lenA - 1), a3i = (3 < lenA) ? 3 : (lenA - 1);
    const int b2i = (2 < lenB) ? 2 : (lenB - 1), b3i = (3 < lenB) ? 3 : (lenB - 1);
    float L1Aa = __ldg(lgA + a2i * CC + r1), L1Ab = __ldg(lgA + a2i * CC + r2);
    float L2Aa = __ldg(lgA + a3i * CC + r1), L2Ab = __ldg(lgA + a3i * CC + r2);
    float L1Ba = __ldg(lgB + b2i * CC + r1), L1Bb = __ldg(lgB + b2i * CC + r2);
    float L2Ba = __ldg(lgB + b3i * CC + r1), L2Bb = __ldg(lgB + b3i * CC + r2);

    float rnA = 1.0f, lnAppA = 0.0f, caccA = 0.0f;
    float rnB = 1.0f, lnAppB = 0.0f, caccB = 0.0f;
    int bufA = 0, bufB = 0;
    const u32 FULL = 0xffffffffu;

    for (int t = 1; t < lenA; ++t) {
        const bool actB = (t < lenB);               // warp-uniform

        // ---- prefetch + F pipeline, seq A
        const int tnA = (t + 3 < lenA) ? (t + 3) : (lenA - 1);
        const float LnAa = __ldg(lgA + tnA * CC + r1);
        const float LnAb = __ldg(lgA + tnA * CC + r2);
        const float FnAa = __expf(L1Aa);
        const float FnAb = __expf(L1Ab);

        // ---- B fragments, seq A
        const u32* wpA = (const u32*)(&wsh[wid][0][bufA][0]);
        u32 a_b0[4], a_b1[4];
        #pragma unroll
        for (int kt = 0; kt < 4; ++kt) {
            a_b0[kt] = wpA[8 * kt + tig];
            a_b1[kt] = wpA[8 * kt + tig + 4];
        }

        // ---- HMMA, seq A (kt outer, mt inner: adjacent instrs independent)
        float cA[4][4];
        #pragma unroll
        for (int mt = 0; mt < 4; ++mt)
            #pragma unroll
            for (int i = 0; i < 4; ++i) cA[mt][i] = 0.0f;
        #pragma unroll
        for (int kt = 0; kt < 4; ++kt)
            #pragma unroll
            for (int mt = 0; mt < 4; ++mt)
                mma16816(cA[mt][0], cA[mt][1], cA[mt][2], cA[mt][3],
                         EA[mt][kt][0], EA[mt][kt][1], EA[mt][kt][2], EA[mt][kt][3],
                         a_b0[kt], a_b1[kt]);

        // ---- seq B: issues into A's chain shadow
        if (actB) {
            const int tnB = (t + 3 < lenB) ? (t + 3) : (lenB - 1);
            const float LnBa = __ldg(lgB + tnB * CC + r1);
            const float LnBb = __ldg(lgB + tnB * CC + r2);
            const float FnBa = __expf(L1Ba);
            const float FnBb = __expf(L1Bb);

            const u32* wpB = (const u32*)(&wsh[wid][1][bufB][0]);
            u32 b_b0[4], b_b1[4];
            #pragma unroll
            for (int kt = 0; kt < 4; ++kt) {
                b_b0[kt] = wpB[8 * kt + tig];
                b_b1[kt] = wpB[8 * kt + tig + 4];
            }

            float cB[4][4];
            #pragma unroll
            for (int mt = 0; mt < 4; ++mt)
                #pragma unroll
                for (int i = 0; i < 4; ++i) cB[mt][i] = 0.0f;
            #pragma unroll
            for (int kt = 0; kt < 4; ++kt)
                #pragma unroll
                for (int mt = 0; mt < 4; ++mt)
                    mma16816(cB[mt][0], cB[mt][1], cB[mt][2], cB[mt][3],
                             EA[mt][kt][0], EA[mt][kt][1], EA[mt][kt][2], EA[mt][kt][3],
                             b_b0[kt], b_b1[kt]);

            float D1 = cB[0][0], D2 = cB[0][2];
            if (tig == 1) { D1 = cB[1][0]; D2 = cB[1][2]; }
            if (tig == 2) { D1 = cB[2][0]; D2 = cB[2][2]; }
            if (tig == 3) { D1 = cB[3][0]; D2 = cB[3][2]; }

            w1B = D1 * F1B * rnB;
            w2B = D2 * F2B * rnB;
            wsh[wid][1][bufB ^ 1][r1] = f2bf(w1B);
            wsh[wid][1][bufB ^ 1][r2] = f2bf(w2B);
            bufB ^= 1;

            caccB += lnAppB;
            float vb = __shfl_sync(FULL, w1B, 0);
            vb = fminf(fmaxf(vb, 1e-30f), 1e30f);
            rnB = frcp(vb);
            lnAppB = -__logf(rnB);

            F1B = FnBa; F2B = FnBb;
            L1Ba = L2Ba; L1Bb = L2Bb;
            L2Ba = LnBa; L2Bb = LnBb;
        }

        // ---- seq A epilogue (chains done by now)
        float D1 = cA[0][0], D2 = cA[0][2];
        if (tig == 1) { D1 = cA[1][0]; D2 = cA[1][2]; }
        if (tig == 2) { D1 = cA[2][0]; D2 = cA[2][2]; }
        if (tig == 3) { D1 = cA[3][0]; D2 = cA[3][2]; }

        w1A = D1 * F1A * rnA;
        w2A = D2 * F2A * rnA;
        wsh[wid][0][bufA ^ 1][r1] = f2bf(w1A);
        wsh[wid][0][bufA ^ 1][r2] = f2bf(w2A);
        bufA ^= 1;

        caccA += lnAppA;
        float vb = __shfl_sync(FULL, w1A, 0);
        vb = fminf(fmaxf(vb, 1e-30f), 1e30f);
        rnA = frcp(vb);
        lnAppA = -__logf(rnA);

        F1A = FnAa; F2A = FnAb;
        L1Aa = L2Aa; L1Ab = L2Ab;
        L2Aa = LnAa; L2Ab = LnAb;

        __syncwarp();                               // covers both sequences
    }

    // ---- finalize both sequences
    #pragma unroll
    for (int sq = 0; sq < 2; ++sq) {
        const int   g    = sq ? gB : gA;
        const int   len  = sq ? lenB : lenA;
        const float cacc = sq ? caccB : caccA;
        float s = sq ? (w1B + w2B) : (w1A + w2A);
        #pragma unroll
        for (int o = 16; o; o >>= 1) s += __shfl_xor_sync(FULL, s, o);
        const float logZ = cacc + __logf(s);

        const float* lg = sq ? lgB : lgA;
        const int* tg = tags + (size_t)g * TT;
        const int tg0 = __ldg(tg);
        const float first = __ldg(init + tg0) + __ldg(lg + tg0);
        float gs = 0.0f;
        for (int t = 1 + lane; t < len; t += 32) {
            const int tc = __ldg(tg + t);
            const int tp = __ldg(tg + t - 1);
            gs += __ldg(trans + tc * CC + tp) + __ldg(lg + t * CC + tc);
        }
        #pragma unroll
        for (int o = 16; o; o >>= 1) gs += __shfl_xor_sync(FULL, gs, o);

        if (lane == 0) out[g] = logZ - (first + gs);
    }
}

extern "C" void kernel_launch(void* const* d_in, const int* in_sizes, int n_in,
                              void* d_out, int out_size)
{
    const float* logits = (const float*)d_in[0];
    const float* trans  = (const float*)d_in[1];
    const float* init   = (const float*)d_in[2];
    const int*   lens   = (const int*)  d_in[3];
    const int*   tags   = (const int*)  d_in[4];
    float*       out    = (float*)d_out;

    rank_kernel<<<1, NB>>>(lens);
    crf_fwd_kernel<<<NB / 8, 128>>>(logits, trans, init, lens, tags, out);
}